// round 1
// baseline (speedup 1.0000x reference)
#include <cuda_runtime.h>

#define BSZ   8
#define NSEQ  2048
#define EDIM  128
#define HEADS 4
#define DHEAD 32
#define NEGV  -1e9f
#define QSCALE 0.17677669529663687f  // 1/sqrt(32)

// Scratch (static __device__ — no allocations allowed)
__device__ float g_q[(size_t)BSZ * HEADS * NSEQ * DHEAD];
__device__ float g_k[(size_t)BSZ * HEADS * NSEQ * DHEAD];
__device__ float g_v[(size_t)BSZ * HEADS * NSEQ * DHEAD];
__device__ float g_attn[(size_t)BSZ * NSEQ * EDIM];

// ---------------------------------------------------------------------------
// Kernel 1: QKV projection.  qkv[m][c] = sum_e x[m][e] * W[c][e] + b[c]
// M = B*N = 16384 rows, K = 128, 384 output cols, scattered to q/k/v in
// (B*H, N, D) layout.
// Block: 256 threads (16x16), tile 64x64, BK=16, 4x4 per thread.
// ---------------------------------------------------------------------------
__global__ __launch_bounds__(256) void qkv_proj_kernel(
    const float* __restrict__ x, const float* __restrict__ w,
    const float* __restrict__ bias)
{
    __shared__ float As[64][17];
    __shared__ float Bs[64][17];

    const int m0 = blockIdx.y * 64;
    const int c0 = blockIdx.x * 64;
    const int tid = threadIdx.x;
    const int tx = tid & 15, ty = tid >> 4;

    float acc[4][4] = {};

    for (int k0 = 0; k0 < EDIM; k0 += 16) {
        __syncthreads();
        #pragma unroll
        for (int i = tid; i < 64 * 16; i += 256) {
            int r = i >> 4, kk = i & 15;
            As[r][kk] = x[(size_t)(m0 + r) * EDIM + k0 + kk];
            Bs[r][kk] = w[(size_t)(c0 + r) * EDIM + k0 + kk];
        }
        __syncthreads();
        #pragma unroll
        for (int kk = 0; kk < 16; kk++) {
            float a[4], b[4];
            #pragma unroll
            for (int i = 0; i < 4; i++) a[i] = As[ty * 4 + i][kk];
            #pragma unroll
            for (int j = 0; j < 4; j++) b[j] = Bs[tx * 4 + j][kk];
            #pragma unroll
            for (int i = 0; i < 4; i++)
                #pragma unroll
                for (int j = 0; j < 4; j++)
                    acc[i][j] += a[i] * b[j];
        }
    }

    // Scatter epilogue: c in [0,384): part=c/128, e=c%128, h=e/32, d=e%32
    #pragma unroll
    for (int i = 0; i < 4; i++) {
        int m = m0 + ty * 4 + i;
        int b = m >> 11;           // m / NSEQ
        int n = m & (NSEQ - 1);
        #pragma unroll
        for (int j = 0; j < 4; j++) {
            int c = c0 + tx * 4 + j;
            float val = acc[i][j] + bias[c];
            int part = c >> 7;
            int e = c & 127;
            int h = e >> 5;
            int d = e & 31;
            size_t idx = (((size_t)b * HEADS + h) * NSEQ + n) * DHEAD + d;
            if (part == 0)      g_q[idx] = val;
            else if (part == 1) g_k[idx] = val;
            else                g_v[idx] = val;
        }
    }
}

// ---------------------------------------------------------------------------
// Kernel 2: flash attention per (b,h).  Shared additive mask from adj[0].
// Block = 64 query rows, streams 32 key tiles of 64.  256 threads.
// QK: 16x16 thread map, 4x4 scores/thread.  PV: P staged via SMEM,
// each thread accumulates 4 rows x 2 d-cols of O.
// ---------------------------------------------------------------------------
__global__ __launch_bounds__(256) void attn_kernel(const int* __restrict__ adj)
{
    __shared__ float Qs[64][33];
    __shared__ float Ks[64][33];
    __shared__ float Vs[64][33];
    __shared__ float Ps[64][65];

    const int qt = blockIdx.x;    // query tile (0..31)
    const int bh = blockIdx.y;    // (b*H + h)   (0..31)
    const int tid = threadIdx.x;
    const int tx = tid & 15, ty = tid >> 4;

    // Load + pre-scale Q tile
    const float* qb = g_q + ((size_t)bh * NSEQ + (size_t)qt * 64) * DHEAD;
    for (int i = tid; i < 64 * 32; i += 256) {
        int r = i >> 5, d = i & 31;
        Qs[r][d] = qb[i] * QSCALE;
    }

    float m_i[4], l_i[4], acc[4][2];
    #pragma unroll
    for (int i = 0; i < 4; i++) {
        m_i[i] = -1e30f; l_i[i] = 0.f; acc[i][0] = 0.f; acc[i][1] = 0.f;
    }

    const int* mrow = adj + (size_t)(qt * 64) * NSEQ;  // adj[0] slice

    for (int kt = 0; kt < NSEQ / 64; kt++) {
        __syncthreads();   // previous PV done reading Ks/Vs/Ps
        const float* kb = g_k + ((size_t)bh * NSEQ + (size_t)kt * 64) * DHEAD;
        const float* vb = g_v + ((size_t)bh * NSEQ + (size_t)kt * 64) * DHEAD;
        for (int i = tid; i < 64 * 8; i += 256) {
            float4 k4 = ((const float4*)kb)[i];
            float4 v4 = ((const float4*)vb)[i];
            int r = i >> 3, d4 = (i & 7) * 4;
            Ks[r][d4] = k4.x; Ks[r][d4 + 1] = k4.y; Ks[r][d4 + 2] = k4.z; Ks[r][d4 + 3] = k4.w;
            Vs[r][d4] = v4.x; Vs[r][d4 + 1] = v4.y; Vs[r][d4 + 2] = v4.z; Vs[r][d4 + 3] = v4.w;
        }
        __syncthreads();

        // S = Qs @ Ks^T (Q pre-scaled)
        float s[4][4] = {};
        #pragma unroll
        for (int d = 0; d < 32; d++) {
            float a[4], b[4];
            #pragma unroll
            for (int i = 0; i < 4; i++) a[i] = Qs[ty * 4 + i][d];
            #pragma unroll
            for (int j = 0; j < 4; j++) b[j] = Ks[tx * 4 + j][d];
            #pragma unroll
            for (int i = 0; i < 4; i++)
                #pragma unroll
                for (int j = 0; j < 4; j++)
                    s[i][j] += a[i] * b[j];
        }

        // Additive mask (vectorized int4 read, coalesced across tx)
        #pragma unroll
        for (int i = 0; i < 4; i++) {
            const int4 mv = *(const int4*)(mrow + (size_t)(ty * 4 + i) * NSEQ
                                           + kt * 64 + tx * 4);
            if (mv.x == 0) s[i][0] += NEGV;
            if (mv.y == 0) s[i][1] += NEGV;
            if (mv.z == 0) s[i][2] += NEGV;
            if (mv.w == 0) s[i][3] += NEGV;
        }

        // Online softmax update (row reductions over 16 tx lanes)
        #pragma unroll
        for (int i = 0; i < 4; i++) {
            float rm = fmaxf(fmaxf(s[i][0], s[i][1]), fmaxf(s[i][2], s[i][3]));
            #pragma unroll
            for (int o = 8; o >= 1; o >>= 1)
                rm = fmaxf(rm, __shfl_xor_sync(0xffffffffu, rm, o));
            float mnew = fmaxf(m_i[i], rm);
            float alpha = __expf(m_i[i] - mnew);
            float p0 = __expf(s[i][0] - mnew);
            float p1 = __expf(s[i][1] - mnew);
            float p2 = __expf(s[i][2] - mnew);
            float p3 = __expf(s[i][3] - mnew);
            float rs = (p0 + p1) + (p2 + p3);
            #pragma unroll
            for (int o = 8; o >= 1; o >>= 1)
                rs += __shfl_xor_sync(0xffffffffu, rs, o);
            l_i[i] = l_i[i] * alpha + rs;
            m_i[i] = mnew;
            acc[i][0] *= alpha;
            acc[i][1] *= alpha;
            int r = ty * 4 + i, c = tx * 4;
            Ps[r][c] = p0; Ps[r][c + 1] = p1; Ps[r][c + 2] = p2; Ps[r][c + 3] = p3;
        }
        __syncthreads();

        // O += P @ V   (rows ty*4.., d-cols tx*2..)
        #pragma unroll 4
        for (int kk = 0; kk < 64; kk++) {
            float vv0 = Vs[kk][tx * 2];
            float vv1 = Vs[kk][tx * 2 + 1];
            #pragma unroll
            for (int i = 0; i < 4; i++) {
                float p = Ps[ty * 4 + i][kk];
                acc[i][0] += p * vv0;
                acc[i][1] += p * vv1;
            }
        }
    }

    // Epilogue: normalize + write back in (B, N, E) layout (inverse head perm)
    const int b = bh >> 2, h = bh & 3;
    #pragma unroll
    for (int i = 0; i < 4; i++) {
        int n = qt * 64 + ty * 4 + i;
        float inv = 1.0f / l_i[i];
        float* dst = g_attn + ((size_t)b * NSEQ + n) * EDIM + h * DHEAD + tx * 2;
        dst[0] = acc[i][0] * inv;
        dst[1] = acc[i][1] * inv;
    }
}

// ---------------------------------------------------------------------------
// Kernel 3: output projection.  out[m][c] = sum_e attn[m][e]*Wo[c][e] + bo[c]
// ---------------------------------------------------------------------------
__global__ __launch_bounds__(256) void out_proj_kernel(
    const float* __restrict__ w, const float* __restrict__ bias,
    float* __restrict__ out)
{
    __shared__ float As[64][17];
    __shared__ float Bs[64][17];

    const int m0 = blockIdx.y * 64;
    const int c0 = blockIdx.x * 64;
    const int tid = threadIdx.x;
    const int tx = tid & 15, ty = tid >> 4;

    float acc[4][4] = {};

    for (int k0 = 0; k0 < EDIM; k0 += 16) {
        __syncthreads();
        #pragma unroll
        for (int i = tid; i < 64 * 16; i += 256) {
            int r = i >> 4, kk = i & 15;
            As[r][kk] = g_attn[(size_t)(m0 + r) * EDIM + k0 + kk];
            Bs[r][kk] = w[(size_t)(c0 + r) * EDIM + k0 + kk];
        }
        __syncthreads();
        #pragma unroll
        for (int kk = 0; kk < 16; kk++) {
            float a[4], b[4];
            #pragma unroll
            for (int i = 0; i < 4; i++) a[i] = As[ty * 4 + i][kk];
            #pragma unroll
            for (int j = 0; j < 4; j++) b[j] = Bs[tx * 4 + j][kk];
            #pragma unroll
            for (int i = 0; i < 4; i++)
                #pragma unroll
                for (int j = 0; j < 4; j++)
                    acc[i][j] += a[i] * b[j];
        }
    }

    #pragma unroll
    for (int i = 0; i < 4; i++) {
        int m = m0 + ty * 4 + i;
        #pragma unroll
        for (int j = 0; j < 4; j++) {
            int c = c0 + tx * 4 + j;
            out[(size_t)m * EDIM + c] = acc[i][j] + bias[c];
        }
    }
}

// ---------------------------------------------------------------------------
extern "C" void kernel_launch(void* const* d_in, const int* in_sizes, int n_in,
                              void* d_out, int out_size)
{
    const float* x   = (const float*)d_in[0];   // (8, 2048, 128)
    const int*   adj = (const int*)  d_in[1];   // (8, 2048, 2048) — only [0] used
    const float* ipw = (const float*)d_in[2];   // (384, 128)
    const float* ipb = (const float*)d_in[3];   // (384,)
    const float* ow  = (const float*)d_in[4];   // (128, 128)
    const float* ob  = (const float*)d_in[5];   // (128,)
    float* out = (float*)d_out;                 // (8, 2048, 128)

    (void)in_sizes; (void)n_in; (void)out_size;

    // QKV projection: M=16384 rows, 384 cols → grid (384/64, 16384/64)
    qkv_proj_kernel<<<dim3(6, 256), 256>>>(x, ipw, ipb);

    // Attention: 32 query tiles × 32 (b,h) pairs
    attn_kernel<<<dim3(32, 32), 256>>>(adj);

    // Output projection: 128 cols → grid (2, 256)
    out_proj_kernel<<<dim3(2, 256), 256>>>(ow, ob, out);
}

// round 2
// speedup vs baseline: 2.8011x; 2.8011x over previous
#include <cuda_runtime.h>
#include <cstdint>

#define BSZ   8
#define NSEQ  2048
#define EDIM  128
#define HEADS 4
#define DHEAD 32
#define NEGV  -1e9f
#define QSCALE 0.17677669529663687f  // 1/sqrt(32)

// Scratch (static __device__ — no allocations allowed)
__device__ float    g_q[(size_t)BSZ * HEADS * NSEQ * DHEAD];
__device__ float    g_k[(size_t)BSZ * HEADS * NSEQ * DHEAD];
__device__ float    g_v[(size_t)BSZ * HEADS * NSEQ * DHEAD];
__device__ float    g_attn[(size_t)BSZ * NSEQ * EDIM];
__device__ unsigned g_mask[(size_t)NSEQ * (NSEQ / 32)];   // adj[0] bit-packed

// --------------------------------------------------------------------------
// helpers: tf32 convert + m16n8k8 tf32 mma
// --------------------------------------------------------------------------
__device__ __forceinline__ unsigned f2tf(float f) {
    unsigned r;
    asm("cvt.rna.tf32.f32 %0, %1;" : "=r"(r) : "f"(f));
    return r;
}

__device__ __forceinline__ void mma8(float* c,
                                     unsigned a0, unsigned a1, unsigned a2, unsigned a3,
                                     unsigned b0, unsigned b1) {
    asm volatile(
        "mma.sync.aligned.m16n8k8.row.col.f32.tf32.tf32.f32 "
        "{%0,%1,%2,%3}, {%4,%5,%6,%7}, {%8,%9}, {%0,%1,%2,%3};"
        : "+f"(c[0]), "+f"(c[1]), "+f"(c[2]), "+f"(c[3])
        : "r"(a0), "r"(a1), "r"(a2), "r"(a3), "r"(b0), "r"(b1));
}

// --------------------------------------------------------------------------
// Kernel 0: bit-pack adj[0] (N x N int32 -> N x N/32 words)
// --------------------------------------------------------------------------
__global__ __launch_bounds__(256) void maskpack_kernel(const int* __restrict__ adj) {
    int gid  = blockIdx.x * 256 + threadIdx.x;
    int w    = gid >> 5;          // word index over 2048*64
    int lane = gid & 31;
    int n    = w >> 6;            // row
    int word = w & 63;
    int v = adj[(size_t)n * NSEQ + word * 32 + lane];
    unsigned m = __ballot_sync(0xffffffffu, v != 0);
    if (lane == 0) g_mask[w] = m;
}

// --------------------------------------------------------------------------
// Kernel 1: QKV projection via tf32 mma.  C = X(16384x128) @ W^T(384x128)^T.
// Block: 256 thr (8 warps), tile M=128 x N=64. Scatter to (B*H,N,D) q/k/v.
// --------------------------------------------------------------------------
__global__ __launch_bounds__(256) void qkv_proj_kernel(
    const float* __restrict__ x, const float* __restrict__ w,
    const float* __restrict__ bias)
{
    __shared__ unsigned Xs[128 * 36];   // pitch 36 -> bank = 4g+t+8kc, conflict-free
    __shared__ unsigned Ws[64 * 36];

    const int tid = threadIdx.x;
    const int wp = tid >> 5, lane = tid & 31;
    const int g = lane >> 2, t = lane & 3;
    const int m0 = blockIdx.y * 128, c0 = blockIdx.x * 64;

    float acc[8][4];
    #pragma unroll
    for (int nt = 0; nt < 8; nt++)
        #pragma unroll
        for (int j = 0; j < 4; j++) acc[nt][j] = 0.f;

    for (int ko = 0; ko < EDIM; ko += 32) {
        __syncthreads();
        #pragma unroll
        for (int i = tid; i < 1024; i += 256) {
            int r = i >> 3, c4 = (i & 7) * 4;
            float4 v4 = *(const float4*)&x[(size_t)(m0 + r) * EDIM + ko + c4];
            *(uint4*)&Xs[r * 36 + c4] =
                make_uint4(f2tf(v4.x), f2tf(v4.y), f2tf(v4.z), f2tf(v4.w));
        }
        #pragma unroll
        for (int i = tid; i < 512; i += 256) {
            int r = i >> 3, c4 = (i & 7) * 4;
            float4 v4 = *(const float4*)&w[(size_t)(c0 + r) * EDIM + ko + c4];
            *(uint4*)&Ws[r * 36 + c4] =
                make_uint4(f2tf(v4.x), f2tf(v4.y), f2tf(v4.z), f2tf(v4.w));
        }
        __syncthreads();

        #pragma unroll
        for (int kc = 0; kc < 4; kc++) {
            const unsigned* xr = &Xs[(wp * 16 + g) * 36 + kc * 8 + t];
            unsigned a0 = xr[0], a1 = xr[8 * 36], a2 = xr[4], a3 = xr[8 * 36 + 4];
            #pragma unroll
            for (int nt = 0; nt < 8; nt++) {
                unsigned b0 = Ws[(nt * 8 + g) * 36 + kc * 8 + t];
                unsigned b1 = Ws[(nt * 8 + g) * 36 + kc * 8 + t + 4];
                mma8(acc[nt], a0, a1, a2, a3, b0, b1);
            }
        }
    }

    // epilogue: bias + scatter to q/k/v (B*H, N, D)
    const int mrow0 = m0 + wp * 16 + g;
    #pragma unroll
    for (int nt = 0; nt < 8; nt++) {
        int cg = c0 + nt * 8 + 2 * t;
        float b0v = bias[cg], b1v = bias[cg + 1];
        int part = cg >> 7;
        int e = cg & 127, h = e >> 5, d = e & 31;
        float* base = (part == 0) ? g_q : (part == 1) ? g_k : g_v;
        #pragma unroll
        for (int rr = 0; rr < 2; rr++) {
            int m = mrow0 + rr * 8;
            int bb = m >> 11, n = m & (NSEQ - 1);
            float v0 = acc[nt][rr * 2 + 0] + b0v;
            float v1 = acc[nt][rr * 2 + 1] + b1v;
            *(float2*)&base[(((size_t)bb * HEADS + h) * NSEQ + n) * DHEAD + d] =
                make_float2(v0, v1);
        }
    }
}

// --------------------------------------------------------------------------
// Kernel 2: flash attention, tf32 mma.  Block = 128 thr (4 warps),
// 64 q-rows per block, 64 kv cols per iteration, one (b,h) per blockIdx.y.
// --------------------------------------------------------------------------
__global__ __launch_bounds__(128) void attn_kernel()
{
    __shared__ unsigned Ks[64 * 40];        // [kvrow][d], pitch 40
    __shared__ unsigned Vs[64 * 40];
    __shared__ unsigned Ps[4][16 * 68];     // per-warp P tile, pitch 68

    const int tid = threadIdx.x;
    const int wp = tid >> 5, lane = tid & 31;
    const int g = lane >> 2, t = lane & 3;
    const int qt = blockIdx.x, bh = blockIdx.y;

    const size_t qkv_off = (size_t)bh * NSEQ * DHEAD;
    const int r0 = qt * 64 + wp * 16 + g;    // global q rows owned by thread
    const int r1 = r0 + 8;

    // Q fragments (pre-scaled, tf32), kept in registers for the whole kernel
    unsigned qa[4][4];
    {
        const float* q0 = g_q + qkv_off + (size_t)r0 * DHEAD;
        const float* q1 = g_q + qkv_off + (size_t)r1 * DHEAD;
        #pragma unroll
        for (int kc = 0; kc < 4; kc++) {
            qa[kc][0] = f2tf(q0[kc * 8 + t] * QSCALE);
            qa[kc][1] = f2tf(q1[kc * 8 + t] * QSCALE);
            qa[kc][2] = f2tf(q0[kc * 8 + t + 4] * QSCALE);
            qa[kc][3] = f2tf(q1[kc * 8 + t + 4] * QSCALE);
        }
    }

    float o[4][4];
    #pragma unroll
    for (int nt = 0; nt < 4; nt++)
        #pragma unroll
        for (int j = 0; j < 4; j++) o[nt][j] = 0.f;

    float m0v = -1e30f, m1v = -1e30f, l0 = 0.f, l1 = 0.f;

    const unsigned* mrow0 = &g_mask[(size_t)r0 * 64];
    const unsigned* mrow1 = &g_mask[(size_t)r1 * 64];
    unsigned* Pw = Ps[wp];

    for (int kt = 0; kt < NSEQ / 64; kt++) {
        __syncthreads();   // all warps done reading previous K/V
        const float* kb = g_k + qkv_off + (size_t)kt * 64 * DHEAD;
        const float* vb = g_v + qkv_off + (size_t)kt * 64 * DHEAD;
        #pragma unroll
        for (int i = tid; i < 512; i += 128) {
            int r = i >> 3, c4 = (i & 7) * 4;
            float4 k4 = *(const float4*)&kb[(size_t)r * DHEAD + c4];
            float4 v4 = *(const float4*)&vb[(size_t)r * DHEAD + c4];
            *(uint4*)&Ks[r * 40 + c4] =
                make_uint4(f2tf(k4.x), f2tf(k4.y), f2tf(k4.z), f2tf(k4.w));
            *(uint4*)&Vs[r * 40 + c4] =
                make_uint4(f2tf(v4.x), f2tf(v4.y), f2tf(v4.z), f2tf(v4.w));
        }
        __syncthreads();

        // S = Q K^T  (16 x 64 per warp)
        float s[8][4] = {};
        #pragma unroll
        for (int kc = 0; kc < 4; kc++) {
            #pragma unroll
            for (int nt = 0; nt < 8; nt++) {
                unsigned b0 = Ks[(nt * 8 + g) * 40 + kc * 8 + t];
                unsigned b1 = Ks[(nt * 8 + g) * 40 + kc * 8 + t + 4];
                mma8(s[nt], qa[kc][0], qa[kc][1], qa[kc][2], qa[kc][3], b0, b1);
            }
        }

        // additive mask from packed bits
        uint2 mw0 = *(const uint2*)&mrow0[kt * 2];
        uint2 mw1 = *(const uint2*)&mrow1[kt * 2];
        #pragma unroll
        for (int nt = 0; nt < 8; nt++) {
            int sh = (nt * 8 + 2 * t) & 31;
            unsigned w0 = (nt < 4) ? mw0.x : mw0.y;
            unsigned w1 = (nt < 4) ? mw1.x : mw1.y;
            if (!((w0 >> sh) & 1))       s[nt][0] += NEGV;
            if (!((w0 >> (sh + 1)) & 1)) s[nt][1] += NEGV;
            if (!((w1 >> sh) & 1))       s[nt][2] += NEGV;
            if (!((w1 >> (sh + 1)) & 1)) s[nt][3] += NEGV;
        }

        // online softmax (rows r0, r1); l kept lane-partial, reduced at end
        float rm0 = -1e30f, rm1 = -1e30f;
        #pragma unroll
        for (int nt = 0; nt < 8; nt++) {
            rm0 = fmaxf(rm0, fmaxf(s[nt][0], s[nt][1]));
            rm1 = fmaxf(rm1, fmaxf(s[nt][2], s[nt][3]));
        }
        rm0 = fmaxf(rm0, __shfl_xor_sync(0xffffffffu, rm0, 1));
        rm0 = fmaxf(rm0, __shfl_xor_sync(0xffffffffu, rm0, 2));
        rm1 = fmaxf(rm1, __shfl_xor_sync(0xffffffffu, rm1, 1));
        rm1 = fmaxf(rm1, __shfl_xor_sync(0xffffffffu, rm1, 2));

        float mn0 = fmaxf(m0v, rm0), mn1 = fmaxf(m1v, rm1);
        float al0 = __expf(m0v - mn0), al1 = __expf(m1v - mn1);
        m0v = mn0; m1v = mn1;

        float ps0 = 0.f, ps1 = 0.f;
        #pragma unroll
        for (int nt = 0; nt < 8; nt++) {
            float p0 = __expf(s[nt][0] - mn0);
            float p1 = __expf(s[nt][1] - mn0);
            float p2 = __expf(s[nt][2] - mn1);
            float p3 = __expf(s[nt][3] - mn1);
            ps0 += p0 + p1;
            ps1 += p2 + p3;
            int c = nt * 8 + 2 * t;
            *(uint2*)&Pw[g * 68 + c]       = make_uint2(f2tf(p0), f2tf(p1));
            *(uint2*)&Pw[(g + 8) * 68 + c] = make_uint2(f2tf(p2), f2tf(p3));
        }
        l0 = l0 * al0 + ps0;
        l1 = l1 * al1 + ps1;
        #pragma unroll
        for (int nt = 0; nt < 4; nt++) {
            o[nt][0] *= al0; o[nt][1] *= al0;
            o[nt][2] *= al1; o[nt][3] *= al1;
        }
        __syncwarp();

        // O += P @ V   (16 x 32 per warp)
        #pragma unroll
        for (int kc = 0; kc < 8; kc++) {
            unsigned pa0 = Pw[g * 68 + kc * 8 + t];
            unsigned pa1 = Pw[(g + 8) * 68 + kc * 8 + t];
            unsigned pa2 = Pw[g * 68 + kc * 8 + t + 4];
            unsigned pa3 = Pw[(g + 8) * 68 + kc * 8 + t + 4];
            #pragma unroll
            for (int nt = 0; nt < 4; nt++) {
                unsigned vb0 = Vs[(kc * 8 + t) * 40 + nt * 8 + g];
                unsigned vb1 = Vs[(kc * 8 + t + 4) * 40 + nt * 8 + g];
                mma8(o[nt], pa0, pa1, pa2, pa3, vb0, vb1);
            }
        }
        __syncwarp();
    }

    // epilogue: reduce l over the 4 lanes of each row group, normalize, store
    l0 += __shfl_xor_sync(0xffffffffu, l0, 1);
    l0 += __shfl_xor_sync(0xffffffffu, l0, 2);
    l1 += __shfl_xor_sync(0xffffffffu, l1, 1);
    l1 += __shfl_xor_sync(0xffffffffu, l1, 2);
    float inv0 = 1.f / l0, inv1 = 1.f / l1;

    const int b = bh >> 2, h = bh & 3;
    float* d0 = g_attn + ((size_t)b * NSEQ + r0) * EDIM + h * DHEAD;
    float* d1 = g_attn + ((size_t)b * NSEQ + r1) * EDIM + h * DHEAD;
    #pragma unroll
    for (int nt = 0; nt < 4; nt++) {
        int c = nt * 8 + 2 * t;
        *(float2*)&d0[c] = make_float2(o[nt][0] * inv0, o[nt][1] * inv0);
        *(float2*)&d1[c] = make_float2(o[nt][2] * inv1, o[nt][3] * inv1);
    }
}

// --------------------------------------------------------------------------
// Kernel 3: output projection via tf32 mma. out = attn(16384x128) @ Wo^T + b
// --------------------------------------------------------------------------
__global__ __launch_bounds__(256) void out_proj_kernel(
    const float* __restrict__ w, const float* __restrict__ bias,
    float* __restrict__ out)
{
    __shared__ unsigned Xs[128 * 36];
    __shared__ unsigned Ws[64 * 36];

    const int tid = threadIdx.x;
    const int wp = tid >> 5, lane = tid & 31;
    const int g = lane >> 2, t = lane & 3;
    const int m0 = blockIdx.y * 128, c0 = blockIdx.x * 64;

    float acc[8][4];
    #pragma unroll
    for (int nt = 0; nt < 8; nt++)
        #pragma unroll
        for (int j = 0; j < 4; j++) acc[nt][j] = 0.f;

    for (int ko = 0; ko < EDIM; ko += 32) {
        __syncthreads();
        #pragma unroll
        for (int i = tid; i < 1024; i += 256) {
            int r = i >> 3, c4 = (i & 7) * 4;
            float4 v4 = *(const float4*)&g_attn[(size_t)(m0 + r) * EDIM + ko + c4];
            *(uint4*)&Xs[r * 36 + c4] =
                make_uint4(f2tf(v4.x), f2tf(v4.y), f2tf(v4.z), f2tf(v4.w));
        }
        #pragma unroll
        for (int i = tid; i < 512; i += 256) {
            int r = i >> 3, c4 = (i & 7) * 4;
            float4 v4 = *(const float4*)&w[(size_t)(c0 + r) * EDIM + ko + c4];
            *(uint4*)&Ws[r * 36 + c4] =
                make_uint4(f2tf(v4.x), f2tf(v4.y), f2tf(v4.z), f2tf(v4.w));
        }
        __syncthreads();

        #pragma unroll
        for (int kc = 0; kc < 4; kc++) {
            const unsigned* xr = &Xs[(wp * 16 + g) * 36 + kc * 8 + t];
            unsigned a0 = xr[0], a1 = xr[8 * 36], a2 = xr[4], a3 = xr[8 * 36 + 4];
            #pragma unroll
            for (int nt = 0; nt < 8; nt++) {
                unsigned b0 = Ws[(nt * 8 + g) * 36 + kc * 8 + t];
                unsigned b1 = Ws[(nt * 8 + g) * 36 + kc * 8 + t + 4];
                mma8(acc[nt], a0, a1, a2, a3, b0, b1);
            }
        }
    }

    const int mrow0 = m0 + wp * 16 + g;
    #pragma unroll
    for (int nt = 0; nt < 8; nt++) {
        int cg = c0 + nt * 8 + 2 * t;
        float b0v = bias[cg], b1v = bias[cg + 1];
        #pragma unroll
        for (int rr = 0; rr < 2; rr++) {
            int m = mrow0 + rr * 8;
            *(float2*)&out[(size_t)m * EDIM + cg] =
                make_float2(acc[nt][rr * 2 + 0] + b0v, acc[nt][rr * 2 + 1] + b1v);
        }
    }
}

// --------------------------------------------------------------------------
extern "C" void kernel_launch(void* const* d_in, const int* in_sizes, int n_in,
                              void* d_out, int out_size)
{
    const float* x   = (const float*)d_in[0];   // (8, 2048, 128)
    const int*   adj = (const int*)  d_in[1];   // (8, 2048, 2048) — only [0] used
    const float* ipw = (const float*)d_in[2];   // (384, 128)
    const float* ipb = (const float*)d_in[3];   // (384,)
    const float* ow  = (const float*)d_in[4];   // (128, 128)
    const float* ob  = (const float*)d_in[5];   // (128,)
    float* out = (float*)d_out;                 // (8, 2048, 128)

    (void)in_sizes; (void)n_in; (void)out_size;

    // Bit-pack adj[0]: 2048 rows x 64 words, one warp per word
    maskpack_kernel<<<16384, 256>>>(adj);

    // QKV projection: M=16384 (128 tiles), N=384 (6 tiles)
    qkv_proj_kernel<<<dim3(6, 128), 256>>>(x, ipw, ipb);

    // Attention: 32 query tiles of 64 x 32 (b,h)
    attn_kernel<<<dim3(32, 32), 128>>>();

    // Output projection: N=128 (2 tiles)
    out_proj_kernel<<<dim3(2, 128), 256>>>(ow, ob, out);
}